// round 15
// baseline (speedup 1.0000x reference)
#include <cuda_runtime.h>

// ---------------------------------------------------------------------------
// TNModel binary-tree TN, B=65536. Round 15:
// Kernel 1 (unchanged from R14): eighth subtree per CTA (w7..w3, 19 KB smem),
//   64 threads, 3 samples/thread, 5 CTAs/SM, prefetch distance 2, __ldcs x.
// Kernel 2: stage-split merge with NO weight staging — all weights read via
//   uniform __ldg (L1 broadcast hits after warmup); smem only for exchanges.
// ---------------------------------------------------------------------------

#define NB       65536
#define T1       64                  // threads, kernel 1
#define SPT      3
#define SPB      (T1 * SPT)          // 192 samples per block
#define BLK_E    342                 // ceil(65536 / 192)
#define NBLOCKS1 (8 * BLK_E)         // 2736
#define HALF     (NB / 2)            // 32768
#define T2       128                 // threads, kernel 2
#define NBLOCKS2 (HALF / 32)         // 1024 (32 sample-pairs per CTA)

// eighth-tree shared-memory float offsets
#define E7 0                      // 16 x 16   =  256
#define E6 (E7 + 256)             //  8 x 128  = 1024
#define E5 (E6 + 1024)            //  4 x 512  = 2048
#define E4 (E5 + 2048)            //  2 x 512  = 1024
#define E3 (E4 + 1024)            //  1 x 512  =  512
#define SMEM1_FLOATS (E3 + 512)   // 4864 floats = 19456 bytes

typedef unsigned long long ull;

__device__ float4 g_ebuf[8 * NB * 2];   // [eighth][sample][2 x float4]

__device__ __forceinline__ ull ffma2(ull a, ull b, ull c) {
    ull d;
    asm("fma.rn.f32x2 %0, %1, %2, %3;" : "=l"(d) : "l"(a), "l"(b), "l"(c));
    return d;
}
__device__ __forceinline__ ull bcast2(float x) {
    ull r;
    asm("mov.b64 %0, {%1, %1};" : "=l"(r) : "f"(x));
    return r;
}
__device__ __forceinline__ void unpack2(ull v, float& lo, float& hi) {
    asm("mov.b64 {%0, %1}, %2;" : "=f"(lo), "=f"(hi) : "l"(v));
}
__device__ __forceinline__ void cp8(float* d, const float* s) {
#pragma unroll
    for (int k = 0; k < 8; ++k) d[k] = s[k];
}

// ---- 3-sample primitives (kernel 1) ----------------------------------------

__device__ __forceinline__ void leaf3(float4 qa, float4 qb, float4 qc,
                                      const float* __restrict__ w,
                                      float* hA, float* hB, float* hC) {
    ull cA0 = 0, cA1 = 0, cB0 = 0, cB1 = 0, cC0 = 0, cC1 = 0;
    float eA[2] = {qa.x, qa.y}, oA[2] = {qa.z, qa.w};
    float eB[2] = {qb.x, qb.y}, oB[2] = {qb.z, qb.w};
    float eC[2] = {qc.x, qc.y}, oC[2] = {qc.z, qc.w};
#pragma unroll
    for (int i = 0; i < 2; ++i) {
#pragma unroll
        for (int j = 0; j < 2; ++j) {
            const ulonglong2 W = *reinterpret_cast<const ulonglong2*>(w + (i * 2 + j) * 4);
            ull p = bcast2(eA[i] * oA[j]);
            cA0 = ffma2(p, W.x, cA0);  cA1 = ffma2(p, W.y, cA1);
            p = bcast2(eB[i] * oB[j]);
            cB0 = ffma2(p, W.x, cB0);  cB1 = ffma2(p, W.y, cB1);
            p = bcast2(eC[i] * oC[j]);
            cC0 = ffma2(p, W.x, cC0);  cC1 = ffma2(p, W.y, cC1);
        }
    }
    unpack2(cA0, hA[0], hA[1]);  unpack2(cA1, hA[2], hA[3]);
    unpack2(cB0, hB[0], hB[1]);  unpack2(cB1, hB[2], hB[3]);
    unpack2(cC0, hC[0], hC[1]);  unpack2(cC1, hC[2], hC[3]);
}

__device__ __forceinline__ void contract448_3(const float* aA, const float* bA,
                                              const float* aB, const float* bB,
                                              const float* aC, const float* bC,
                                              const float* __restrict__ w,
                                              float* outA, float* outB, float* outC) {
    ull cA[4] = {0,0,0,0}, cB[4] = {0,0,0,0}, cC[4] = {0,0,0,0};
#pragma unroll
    for (int i = 0; i < 4; ++i) {
        ull tA[4] = {0,0,0,0}, tB[4] = {0,0,0,0}, tC[4] = {0,0,0,0};
#pragma unroll
        for (int j = 0; j < 4; ++j) {
            const ulonglong2* wp = reinterpret_cast<const ulonglong2*>(w + (i * 4 + j) * 8);
            ulonglong2 W01 = wp[0];
            ulonglong2 W23 = wp[1];
            ull bb = bcast2(bA[j]);
            tA[0] = ffma2(bb, W01.x, tA[0]);  tA[1] = ffma2(bb, W01.y, tA[1]);
            tA[2] = ffma2(bb, W23.x, tA[2]);  tA[3] = ffma2(bb, W23.y, tA[3]);
            bb = bcast2(bB[j]);
            tB[0] = ffma2(bb, W01.x, tB[0]);  tB[1] = ffma2(bb, W01.y, tB[1]);
            tB[2] = ffma2(bb, W23.x, tB[2]);  tB[3] = ffma2(bb, W23.y, tB[3]);
            bb = bcast2(bC[j]);
            tC[0] = ffma2(bb, W01.x, tC[0]);  tC[1] = ffma2(bb, W01.y, tC[1]);
            tC[2] = ffma2(bb, W23.x, tC[2]);  tC[3] = ffma2(bb, W23.y, tC[3]);
        }
        ull ai = bcast2(aA[i]);
        cA[0] = ffma2(ai, tA[0], cA[0]);  cA[1] = ffma2(ai, tA[1], cA[1]);
        cA[2] = ffma2(ai, tA[2], cA[2]);  cA[3] = ffma2(ai, tA[3], cA[3]);
        ai = bcast2(aB[i]);
        cB[0] = ffma2(ai, tB[0], cB[0]);  cB[1] = ffma2(ai, tB[1], cB[1]);
        cB[2] = ffma2(ai, tB[2], cB[2]);  cB[3] = ffma2(ai, tB[3], cB[3]);
        ai = bcast2(aC[i]);
        cC[0] = ffma2(ai, tC[0], cC[0]);  cC[1] = ffma2(ai, tC[1], cC[1]);
        cC[2] = ffma2(ai, tC[2], cC[2]);  cC[3] = ffma2(ai, tC[3], cC[3]);
    }
    unpack2(cA[0], outA[0], outA[1]);  unpack2(cA[1], outA[2], outA[3]);
    unpack2(cA[2], outA[4], outA[5]);  unpack2(cA[3], outA[6], outA[7]);
    unpack2(cB[0], outB[0], outB[1]);  unpack2(cB[1], outB[2], outB[3]);
    unpack2(cB[2], outB[4], outB[5]);  unpack2(cB[3], outB[6], outB[7]);
    unpack2(cC[0], outC[0], outC[1]);  unpack2(cC[1], outC[2], outC[3]);
    unpack2(cC[2], outC[4], outC[5]);  unpack2(cC[3], outC[6], outC[7]);
}

// 8x8->8, three samples sharing W (512 floats, smem), prefetch distance 2.
// out may alias b.
__device__ __forceinline__ void contract888_3(const float* aA, const float* bA,
                                              const float* aB, const float* bB,
                                              const float* aC, const float* bC,
                                              const float* __restrict__ w,
                                              float* outA, float* outB, float* outC) {
    const ulonglong2* wp = reinterpret_cast<const ulonglong2*>(w);
    ull cA[4] = {0,0,0,0}, cB[4] = {0,0,0,0}, cC[4] = {0,0,0,0};
    ulonglong2 W0a = wp[0], W0b = wp[1];
    ulonglong2 W1a = wp[2], W1b = wp[3];
#pragma unroll
    for (int i = 0; i < 8; ++i) {
        ull tA[4] = {0,0,0,0}, tB[4] = {0,0,0,0}, tC[4] = {0,0,0,0};
#pragma unroll
        for (int j = 0; j < 8; ++j) {
            const int nidx = i * 8 + j + 2;
            ulonglong2 nWa, nWb;
            if (nidx < 64) {
                nWa = wp[2 * nidx];
                nWb = wp[2 * nidx + 1];
            }
            ull bb = bcast2(bA[j]);
            tA[0] = ffma2(bb, W0a.x, tA[0]);  tA[1] = ffma2(bb, W0a.y, tA[1]);
            tA[2] = ffma2(bb, W0b.x, tA[2]);  tA[3] = ffma2(bb, W0b.y, tA[3]);
            bb = bcast2(bB[j]);
            tB[0] = ffma2(bb, W0a.x, tB[0]);  tB[1] = ffma2(bb, W0a.y, tB[1]);
            tB[2] = ffma2(bb, W0b.x, tB[2]);  tB[3] = ffma2(bb, W0b.y, tB[3]);
            bb = bcast2(bC[j]);
            tC[0] = ffma2(bb, W0a.x, tC[0]);  tC[1] = ffma2(bb, W0a.y, tC[1]);
            tC[2] = ffma2(bb, W0b.x, tC[2]);  tC[3] = ffma2(bb, W0b.y, tC[3]);
            W0a = W1a;  W0b = W1b;
            if (nidx < 64) { W1a = nWa; W1b = nWb; }
        }
        ull ai = bcast2(aA[i]);
        cA[0] = ffma2(ai, tA[0], cA[0]);  cA[1] = ffma2(ai, tA[1], cA[1]);
        cA[2] = ffma2(ai, tA[2], cA[2]);  cA[3] = ffma2(ai, tA[3], cA[3]);
        ai = bcast2(aB[i]);
        cB[0] = ffma2(ai, tB[0], cB[0]);  cB[1] = ffma2(ai, tB[1], cB[1]);
        cB[2] = ffma2(ai, tB[2], cB[2]);  cB[3] = ffma2(ai, tB[3], cB[3]);
        ai = bcast2(aC[i]);
        cC[0] = ffma2(ai, tC[0], cC[0]);  cC[1] = ffma2(ai, tC[1], cC[1]);
        cC[2] = ffma2(ai, tC[2], cC[2]);  cC[3] = ffma2(ai, tC[3], cC[3]);
    }
    unpack2(cA[0], outA[0], outA[1]);  unpack2(cA[1], outA[2], outA[3]);
    unpack2(cA[2], outA[4], outA[5]);  unpack2(cA[3], outA[6], outA[7]);
    unpack2(cB[0], outB[0], outB[1]);  unpack2(cB[1], outB[2], outB[3]);
    unpack2(cB[2], outB[4], outB[5]);  unpack2(cB[3], outB[6], outB[7]);
    unpack2(cC[0], outC[0], outC[1]);  unpack2(cC[1], outC[2], outC[3]);
    unpack2(cC[2], outC[4], outC[5]);  unpack2(cC[3], outC[6], outC[7]);
}

// ---- merge-kernel contractions: weights via uniform __ldg (global/L1) ------
__device__ __forceinline__ void contract888_2g(const float* aA, const float* bA,
                                               const float* aB, const float* bB,
                                               const float* __restrict__ wg,
                                               float* outA, float* outB) {
    const ulonglong2* wp = reinterpret_cast<const ulonglong2*>(wg);
    ull cA[4] = {0,0,0,0}, cB[4] = {0,0,0,0};
    ulonglong2 W0a = __ldg(wp + 0), W0b = __ldg(wp + 1);
    ulonglong2 W1a = __ldg(wp + 2), W1b = __ldg(wp + 3);
#pragma unroll
    for (int i = 0; i < 8; ++i) {
        ull tA[4] = {0,0,0,0}, tB[4] = {0,0,0,0};
#pragma unroll
        for (int j = 0; j < 8; ++j) {
            const int nidx = i * 8 + j + 2;
            ulonglong2 nWa, nWb;
            if (nidx < 64) {
                nWa = __ldg(wp + 2 * nidx);
                nWb = __ldg(wp + 2 * nidx + 1);
            }
            ull bb = bcast2(bA[j]);
            tA[0] = ffma2(bb, W0a.x, tA[0]);  tA[1] = ffma2(bb, W0a.y, tA[1]);
            tA[2] = ffma2(bb, W0b.x, tA[2]);  tA[3] = ffma2(bb, W0b.y, tA[3]);
            bb = bcast2(bB[j]);
            tB[0] = ffma2(bb, W0a.x, tB[0]);  tB[1] = ffma2(bb, W0a.y, tB[1]);
            tB[2] = ffma2(bb, W0b.x, tB[2]);  tB[3] = ffma2(bb, W0b.y, tB[3]);
            W0a = W1a;  W0b = W1b;
            if (nidx < 64) { W1a = nWa; W1b = nWb; }
        }
        ull ai = bcast2(aA[i]);
        cA[0] = ffma2(ai, tA[0], cA[0]);  cA[1] = ffma2(ai, tA[1], cA[1]);
        cA[2] = ffma2(ai, tA[2], cA[2]);  cA[3] = ffma2(ai, tA[3], cA[3]);
        ai = bcast2(aB[i]);
        cB[0] = ffma2(ai, tB[0], cB[0]);  cB[1] = ffma2(ai, tB[1], cB[1]);
        cB[2] = ffma2(ai, tB[2], cB[2]);  cB[3] = ffma2(ai, tB[3], cB[3]);
    }
    unpack2(cA[0], outA[0], outA[1]);  unpack2(cA[1], outA[2], outA[3]);
    unpack2(cA[2], outA[4], outA[5]);  unpack2(cA[3], outA[6], outA[7]);
    unpack2(cB[0], outB[0], outB[1]);  unpack2(cB[1], outB[2], outB[3]);
    unpack2(cB[2], outB[4], outB[5]);  unpack2(cB[3], outB[6], outB[7]);
}

__device__ __forceinline__ void contract888_1g(const float* a, const float* b,
                                               const float* __restrict__ wg, float* out) {
    const ulonglong2* wp = reinterpret_cast<const ulonglong2*>(wg);
    ull c[4] = {0,0,0,0};
    ulonglong2 W0a = __ldg(wp + 0), W0b = __ldg(wp + 1);
    ulonglong2 W1a = __ldg(wp + 2), W1b = __ldg(wp + 3);
#pragma unroll
    for (int i = 0; i < 8; ++i) {
        ull t[4] = {0,0,0,0};
#pragma unroll
        for (int j = 0; j < 8; ++j) {
            const int nidx = i * 8 + j + 2;
            ulonglong2 nWa, nWb;
            if (nidx < 64) {
                nWa = __ldg(wp + 2 * nidx);
                nWb = __ldg(wp + 2 * nidx + 1);
            }
            ull bb = bcast2(b[j]);
            t[0] = ffma2(bb, W0a.x, t[0]);  t[1] = ffma2(bb, W0a.y, t[1]);
            t[2] = ffma2(bb, W0b.x, t[2]);  t[3] = ffma2(bb, W0b.y, t[3]);
            W0a = W1a;  W0b = W1b;
            if (nidx < 64) { W1a = nWa; W1b = nWb; }
        }
        ull ai = bcast2(a[i]);
        c[0] = ffma2(ai, t[0], c[0]);  c[1] = ffma2(ai, t[1], c[1]);
        c[2] = ffma2(ai, t[2], c[2]);  c[3] = ffma2(ai, t[3], c[3]);
    }
    unpack2(c[0], out[0], out[1]);  unpack2(c[1], out[2], out[3]);
    unpack2(c[2], out[4], out[5]);  unpack2(c[3], out[6], out[7]);
}

__device__ __forceinline__ void scopy4(float* dst, const float* __restrict__ src, int n4) {
    const float4* s = reinterpret_cast<const float4*>(src);
    float4* d = reinterpret_cast<float4*>(dst);
    for (int i = threadIdx.x; i < n4; i += blockDim.x) d[i] = s[i];
}

__device__ __forceinline__ void store_pair(float4* buf, int b, const float* v) {
    buf[(size_t)b * 2 + 0] = make_float4(v[0], v[1], v[2], v[3]);
    buf[(size_t)b * 2 + 1] = make_float4(v[4], v[5], v[6], v[7]);
}

// ------------------------------- kernel 1 ----------------------------------
__global__ void __launch_bounds__(T1, 5)
tn_eighth_kernel(const float* __restrict__ x,
                 const float* __restrict__ w7, const float* __restrict__ w6,
                 const float* __restrict__ w5, const float* __restrict__ w4,
                 const float* __restrict__ w3) {
    extern __shared__ float sw[];

    const int e   = blockIdx.x / BLK_E;      // eighth 0..7
    const int blk = blockIdx.x - e * BLK_E;  // 0..341

    scopy4(sw + E7, w7 + e * 256,   256 / 4);
    scopy4(sw + E6, w6 + e * 1024, 1024 / 4);
    scopy4(sw + E5, w5 + e * 2048, 2048 / 4);
    scopy4(sw + E4, w4 + e * 1024, 1024 / 4);
    scopy4(sw + E3, w3 + e * 512,   512 / 4);
    __syncthreads();

    const int b0 = blk * SPB + threadIdx.x;
    int b1 = b0 + T1;
    int b2 = b0 + 2 * T1;
    if (b1 >= NB) b1 = b0;
    if (b2 >= NB) b2 = b0;

    const float4* xA = reinterpret_cast<const float4*>(x) + (size_t)b0 * 128 + e * 16;
    const float4* xB = reinterpret_cast<const float4*>(x) + (size_t)b1 * 128 + e * 16;
    const float4* xC = reinterpret_cast<const float4*>(x) + (size_t)b2 * 128 + e * 16;

    float stkA0[8], stkA1[8], stkA2[8];
    float stkB0[8], stkB1[8], stkB2[8];
    float stkC0[8], stkC1[8], stkC2[8];

#pragma unroll 1
    for (int m = 0; m < 8; ++m) {
        float4 qA0 = __ldcs(xA + 2 * m);
        float4 qA1 = __ldcs(xA + 2 * m + 1);
        float4 qB0 = __ldcs(xB + 2 * m);
        float4 qB1 = __ldcs(xB + 2 * m + 1);
        float4 qC0 = __ldcs(xC + 2 * m);
        float4 qC1 = __ldcs(xC + 2 * m + 1);

        float laA[4], lbA[4], laB[4], lbB[4], laC[4], lbC[4];
        leaf3(qA0, qB0, qC0, sw + E7 + (2 * m) * 16, laA, laB, laC);
        leaf3(qA1, qB1, qC1, sw + E7 + (2 * m + 1) * 16, lbA, lbB, lbC);

        float curA[8], curB[8], curC[8];
        contract448_3(laA, lbA, laB, lbB, laC, lbC, sw + E6 + m * 128,
                      curA, curB, curC);

        if (!(m & 1)) {
            cp8(stkA0, curA);  cp8(stkB0, curB);  cp8(stkC0, curC);
        } else {
            contract888_3(stkA0, curA, stkB0, curB, stkC0, curC,
                          sw + E5 + (m >> 1) * 512, curA, curB, curC);
            if (!((m >> 1) & 1)) {
                cp8(stkA1, curA);  cp8(stkB1, curB);  cp8(stkC1, curC);
            } else {
                contract888_3(stkA1, curA, stkB1, curB, stkC1, curC,
                              sw + E4 + (m >> 2) * 512, curA, curB, curC);
                if (!((m >> 2) & 1)) {
                    cp8(stkA2, curA);  cp8(stkB2, curB);  cp8(stkC2, curC);
                } else {
                    // m == 7: top of this eighth (w3 node)
                    contract888_3(stkA2, curA, stkB2, curB, stkC2, curC,
                                  sw + E3, curA, curB, curC);
                    float4* eb = g_ebuf + ((size_t)e * NB) * 2;
                    store_pair(eb, b0, curA);
                    store_pair(eb, b1, curB);
                    store_pair(eb, b2, curC);
                }
            }
        }
    }
}

// ------------------------------- kernel 2 ----------------------------------
// 4 warps per CTA, 32 sample-pairs per CTA, grid 1024. NO weight staging:
// all weights via uniform __ldg (L1 broadcast hits). smem only for exchanges.
__global__ void __launch_bounds__(T2)
tn_merge_kernel(const float* __restrict__ w2, const float* __restrict__ w1,
                const float* __restrict__ w0, float* __restrict__ out) {
    __shared__ float x1[4][2][32 * 9];   // stage1: [w2 node][class A/B][lane]
    __shared__ float x2[2][2][32 * 9];   // stage2: [side L/R][class A/B][lane]

    const int warp = threadIdx.x >> 5;
    const int lane = threadIdx.x & 31;
    const int bA = blockIdx.x * 32 + lane;
    const int bB = bA + HALF;

    // hoisted g_ebuf loads (8 independent LDG.128 per thread)
    float4 pA0 = __ldg(g_ebuf + ((size_t)(2 * warp + 0) * NB + bA) * 2 + 0);
    float4 pA1 = __ldg(g_ebuf + ((size_t)(2 * warp + 0) * NB + bA) * 2 + 1);
    float4 pA2 = __ldg(g_ebuf + ((size_t)(2 * warp + 1) * NB + bA) * 2 + 0);
    float4 pA3 = __ldg(g_ebuf + ((size_t)(2 * warp + 1) * NB + bA) * 2 + 1);
    float4 pB0 = __ldg(g_ebuf + ((size_t)(2 * warp + 0) * NB + bB) * 2 + 0);
    float4 pB1 = __ldg(g_ebuf + ((size_t)(2 * warp + 0) * NB + bB) * 2 + 1);
    float4 pB2 = __ldg(g_ebuf + ((size_t)(2 * warp + 1) * NB + bB) * 2 + 0);
    float4 pB3 = __ldg(g_ebuf + ((size_t)(2 * warp + 1) * NB + bB) * 2 + 1);

    // ---- stage 1: w2 node = warp (eighths 2*warp, 2*warp+1) ----
    {
        float vA0[8] = {pA0.x, pA0.y, pA0.z, pA0.w, pA1.x, pA1.y, pA1.z, pA1.w};
        float vA1[8] = {pA2.x, pA2.y, pA2.z, pA2.w, pA3.x, pA3.y, pA3.z, pA3.w};
        float vB0[8] = {pB0.x, pB0.y, pB0.z, pB0.w, pB1.x, pB1.y, pB1.z, pB1.w};
        float vB1[8] = {pB2.x, pB2.y, pB2.z, pB2.w, pB3.x, pB3.y, pB3.z, pB3.w};
        float qA[8], qB[8];
        contract888_2g(vA0, vA1, vB0, vB1, w2 + warp * 512, qA, qB);
#pragma unroll
        for (int k = 0; k < 8; ++k) {
            x1[warp][0][lane * 9 + k] = qA[k];
            x1[warp][1][lane * 9 + k] = qB[k];
        }
    }
    __syncthreads();

    // ---- stage 2: one w1 eval per warp ----
    const int side = warp >> 1;
    const int cls  = warp & 1;
    {
        float a[8], b[8], h[8];
#pragma unroll
        for (int k = 0; k < 8; ++k) {
            a[k] = x1[2 * side + 0][cls][lane * 9 + k];
            b[k] = x1[2 * side + 1][cls][lane * 9 + k];
        }
        contract888_1g(a, b, w1 + side * 512, h);
#pragma unroll
        for (int k = 0; k < 8; ++k) x2[side][cls][lane * 9 + k] = h[k];
    }
    __syncthreads();

    // ---- stage 3: roots (warp 0 -> sample A, warp 1 -> sample B) ----
    if (warp < 2) {
        const int c  = warp;
        const int bo = c == 0 ? bA : bB;
        float hL[8], hR[8];
#pragma unroll
        for (int k = 0; k < 8; ++k) {
            hL[k] = x2[0][c][lane * 9 + k];
            hR[k] = x2[1][c][lane * 9 + k];
        }
        ull acc = 0ull;
        const ull* w0p = reinterpret_cast<const ull*>(w0);
#pragma unroll
        for (int i = 0; i < 8; ++i) {
            ull ai = bcast2(hL[i]);
#pragma unroll
            for (int j = 0; j < 8; ++j) {
                ull W = __ldg(w0p + i * 8 + j);
                acc = ffma2(ffma2(ai, bcast2(hR[j]), 0ull), W, acc);
            }
        }
        float r0, r1;
        unpack2(acc, r0, r1);
        reinterpret_cast<float2*>(out)[bo] = make_float2(r0, r1);
    }
}

extern "C" void kernel_launch(void* const* d_in, const int* in_sizes, int n_in,
                              void* d_out, int out_size) {
    const float* x  = (const float*)d_in[0];
    const float* w7 = (const float*)d_in[1];
    const float* w6 = (const float*)d_in[2];
    const float* w5 = (const float*)d_in[3];
    const float* w4 = (const float*)d_in[4];
    const float* w3 = (const float*)d_in[5];
    const float* w2 = (const float*)d_in[6];
    const float* w1 = (const float*)d_in[7];
    const float* w0 = (const float*)d_in[8];
    float* out = (float*)d_out;

    const size_t smem = SMEM1_FLOATS * sizeof(float);
    cudaFuncSetAttribute(tn_eighth_kernel, cudaFuncAttributeMaxDynamicSharedMemorySize, (int)smem);
    tn_eighth_kernel<<<NBLOCKS1, T1, smem>>>(x, w7, w6, w5, w4, w3);
    tn_merge_kernel<<<NBLOCKS2, T2>>>(w2, w1, w0, out);
}

// round 16
// speedup vs baseline: 1.0963x; 1.0963x over previous
#include <cuda_runtime.h>

// ---------------------------------------------------------------------------
// TNModel binary-tree TN, B=65536. Round 16:
// Kernel 1 (R14, best): eighth subtree per CTA (w7..w3, 19 KB smem), 64 thr,
//   3 samples/thread, 5 CTAs/SM, prefetch distance 2, __ldcs on x.
// Kernel 2: stage-split merge, smem-staged weights (R14 style), but T2=256 /
//   grid 512 (64 pairs per CTA): staging traffic + barriers per pair halved.
// ---------------------------------------------------------------------------

#define NB       65536
#define T1       64                  // threads, kernel 1
#define SPT      3
#define SPB      (T1 * SPT)          // 192 samples per block
#define BLK_E    342                 // ceil(65536 / 192)
#define NBLOCKS1 (8 * BLK_E)         // 2736
#define HALF     (NB / 2)            // 32768
#define T2       256                 // threads, kernel 2 (8 warps)
#define NBLOCKS2 (HALF / 64)         // 512 (64 sample-pairs per CTA)

// eighth-tree shared-memory float offsets
#define E7 0                      // 16 x 16   =  256
#define E6 (E7 + 256)             //  8 x 128  = 1024
#define E5 (E6 + 1024)            //  4 x 512  = 2048
#define E4 (E5 + 2048)            //  2 x 512  = 1024
#define E3 (E4 + 1024)            //  1 x 512  =  512
#define SMEM1_FLOATS (E3 + 512)   // 4864 floats = 19456 bytes

typedef unsigned long long ull;

__device__ float4 g_ebuf[8 * NB * 2];   // [eighth][sample][2 x float4]

__device__ __forceinline__ ull ffma2(ull a, ull b, ull c) {
    ull d;
    asm("fma.rn.f32x2 %0, %1, %2, %3;" : "=l"(d) : "l"(a), "l"(b), "l"(c));
    return d;
}
__device__ __forceinline__ ull bcast2(float x) {
    ull r;
    asm("mov.b64 %0, {%1, %1};" : "=l"(r) : "f"(x));
    return r;
}
__device__ __forceinline__ void unpack2(ull v, float& lo, float& hi) {
    asm("mov.b64 {%0, %1}, %2;" : "=f"(lo), "=f"(hi) : "l"(v));
}
__device__ __forceinline__ void cp8(float* d, const float* s) {
#pragma unroll
    for (int k = 0; k < 8; ++k) d[k] = s[k];
}

// ---- 3-sample primitives (kernel 1) ----------------------------------------

__device__ __forceinline__ void leaf3(float4 qa, float4 qb, float4 qc,
                                      const float* __restrict__ w,
                                      float* hA, float* hB, float* hC) {
    ull cA0 = 0, cA1 = 0, cB0 = 0, cB1 = 0, cC0 = 0, cC1 = 0;
    float eA[2] = {qa.x, qa.y}, oA[2] = {qa.z, qa.w};
    float eB[2] = {qb.x, qb.y}, oB[2] = {qb.z, qb.w};
    float eC[2] = {qc.x, qc.y}, oC[2] = {qc.z, qc.w};
#pragma unroll
    for (int i = 0; i < 2; ++i) {
#pragma unroll
        for (int j = 0; j < 2; ++j) {
            const ulonglong2 W = *reinterpret_cast<const ulonglong2*>(w + (i * 2 + j) * 4);
            ull p = bcast2(eA[i] * oA[j]);
            cA0 = ffma2(p, W.x, cA0);  cA1 = ffma2(p, W.y, cA1);
            p = bcast2(eB[i] * oB[j]);
            cB0 = ffma2(p, W.x, cB0);  cB1 = ffma2(p, W.y, cB1);
            p = bcast2(eC[i] * oC[j]);
            cC0 = ffma2(p, W.x, cC0);  cC1 = ffma2(p, W.y, cC1);
        }
    }
    unpack2(cA0, hA[0], hA[1]);  unpack2(cA1, hA[2], hA[3]);
    unpack2(cB0, hB[0], hB[1]);  unpack2(cB1, hB[2], hB[3]);
    unpack2(cC0, hC[0], hC[1]);  unpack2(cC1, hC[2], hC[3]);
}

__device__ __forceinline__ void contract448_3(const float* aA, const float* bA,
                                              const float* aB, const float* bB,
                                              const float* aC, const float* bC,
                                              const float* __restrict__ w,
                                              float* outA, float* outB, float* outC) {
    ull cA[4] = {0,0,0,0}, cB[4] = {0,0,0,0}, cC[4] = {0,0,0,0};
#pragma unroll
    for (int i = 0; i < 4; ++i) {
        ull tA[4] = {0,0,0,0}, tB[4] = {0,0,0,0}, tC[4] = {0,0,0,0};
#pragma unroll
        for (int j = 0; j < 4; ++j) {
            const ulonglong2* wp = reinterpret_cast<const ulonglong2*>(w + (i * 4 + j) * 8);
            ulonglong2 W01 = wp[0];
            ulonglong2 W23 = wp[1];
            ull bb = bcast2(bA[j]);
            tA[0] = ffma2(bb, W01.x, tA[0]);  tA[1] = ffma2(bb, W01.y, tA[1]);
            tA[2] = ffma2(bb, W23.x, tA[2]);  tA[3] = ffma2(bb, W23.y, tA[3]);
            bb = bcast2(bB[j]);
            tB[0] = ffma2(bb, W01.x, tB[0]);  tB[1] = ffma2(bb, W01.y, tB[1]);
            tB[2] = ffma2(bb, W23.x, tB[2]);  tB[3] = ffma2(bb, W23.y, tB[3]);
            bb = bcast2(bC[j]);
            tC[0] = ffma2(bb, W01.x, tC[0]);  tC[1] = ffma2(bb, W01.y, tC[1]);
            tC[2] = ffma2(bb, W23.x, tC[2]);  tC[3] = ffma2(bb, W23.y, tC[3]);
        }
        ull ai = bcast2(aA[i]);
        cA[0] = ffma2(ai, tA[0], cA[0]);  cA[1] = ffma2(ai, tA[1], cA[1]);
        cA[2] = ffma2(ai, tA[2], cA[2]);  cA[3] = ffma2(ai, tA[3], cA[3]);
        ai = bcast2(aB[i]);
        cB[0] = ffma2(ai, tB[0], cB[0]);  cB[1] = ffma2(ai, tB[1], cB[1]);
        cB[2] = ffma2(ai, tB[2], cB[2]);  cB[3] = ffma2(ai, tB[3], cB[3]);
        ai = bcast2(aC[i]);
        cC[0] = ffma2(ai, tC[0], cC[0]);  cC[1] = ffma2(ai, tC[1], cC[1]);
        cC[2] = ffma2(ai, tC[2], cC[2]);  cC[3] = ffma2(ai, tC[3], cC[3]);
    }
    unpack2(cA[0], outA[0], outA[1]);  unpack2(cA[1], outA[2], outA[3]);
    unpack2(cA[2], outA[4], outA[5]);  unpack2(cA[3], outA[6], outA[7]);
    unpack2(cB[0], outB[0], outB[1]);  unpack2(cB[1], outB[2], outB[3]);
    unpack2(cB[2], outB[4], outB[5]);  unpack2(cB[3], outB[6], outB[7]);
    unpack2(cC[0], outC[0], outC[1]);  unpack2(cC[1], outC[2], outC[3]);
    unpack2(cC[2], outC[4], outC[5]);  unpack2(cC[3], outC[6], outC[7]);
}

// 8x8->8, three samples sharing W (512 floats, smem), prefetch distance 2.
// out may alias b.
__device__ __forceinline__ void contract888_3(const float* aA, const float* bA,
                                              const float* aB, const float* bB,
                                              const float* aC, const float* bC,
                                              const float* __restrict__ w,
                                              float* outA, float* outB, float* outC) {
    const ulonglong2* wp = reinterpret_cast<const ulonglong2*>(w);
    ull cA[4] = {0,0,0,0}, cB[4] = {0,0,0,0}, cC[4] = {0,0,0,0};
    ulonglong2 W0a = wp[0], W0b = wp[1];
    ulonglong2 W1a = wp[2], W1b = wp[3];
#pragma unroll
    for (int i = 0; i < 8; ++i) {
        ull tA[4] = {0,0,0,0}, tB[4] = {0,0,0,0}, tC[4] = {0,0,0,0};
#pragma unroll
        for (int j = 0; j < 8; ++j) {
            const int nidx = i * 8 + j + 2;
            ulonglong2 nWa, nWb;
            if (nidx < 64) {
                nWa = wp[2 * nidx];
                nWb = wp[2 * nidx + 1];
            }
            ull bb = bcast2(bA[j]);
            tA[0] = ffma2(bb, W0a.x, tA[0]);  tA[1] = ffma2(bb, W0a.y, tA[1]);
            tA[2] = ffma2(bb, W0b.x, tA[2]);  tA[3] = ffma2(bb, W0b.y, tA[3]);
            bb = bcast2(bB[j]);
            tB[0] = ffma2(bb, W0a.x, tB[0]);  tB[1] = ffma2(bb, W0a.y, tB[1]);
            tB[2] = ffma2(bb, W0b.x, tB[2]);  tB[3] = ffma2(bb, W0b.y, tB[3]);
            bb = bcast2(bC[j]);
            tC[0] = ffma2(bb, W0a.x, tC[0]);  tC[1] = ffma2(bb, W0a.y, tC[1]);
            tC[2] = ffma2(bb, W0b.x, tC[2]);  tC[3] = ffma2(bb, W0b.y, tC[3]);
            W0a = W1a;  W0b = W1b;
            if (nidx < 64) { W1a = nWa; W1b = nWb; }
        }
        ull ai = bcast2(aA[i]);
        cA[0] = ffma2(ai, tA[0], cA[0]);  cA[1] = ffma2(ai, tA[1], cA[1]);
        cA[2] = ffma2(ai, tA[2], cA[2]);  cA[3] = ffma2(ai, tA[3], cA[3]);
        ai = bcast2(aB[i]);
        cB[0] = ffma2(ai, tB[0], cB[0]);  cB[1] = ffma2(ai, tB[1], cB[1]);
        cB[2] = ffma2(ai, tB[2], cB[2]);  cB[3] = ffma2(ai, tB[3], cB[3]);
        ai = bcast2(aC[i]);
        cC[0] = ffma2(ai, tC[0], cC[0]);  cC[1] = ffma2(ai, tC[1], cC[1]);
        cC[2] = ffma2(ai, tC[2], cC[2]);  cC[3] = ffma2(ai, tC[3], cC[3]);
    }
    unpack2(cA[0], outA[0], outA[1]);  unpack2(cA[1], outA[2], outA[3]);
    unpack2(cA[2], outA[4], outA[5]);  unpack2(cA[3], outA[6], outA[7]);
    unpack2(cB[0], outB[0], outB[1]);  unpack2(cB[1], outB[2], outB[3]);
    unpack2(cB[2], outB[4], outB[5]);  unpack2(cB[3], outB[6], outB[7]);
    unpack2(cC[0], outC[0], outC[1]);  unpack2(cC[1], outC[2], outC[3]);
    unpack2(cC[2], outC[4], outC[5]);  unpack2(cC[3], outC[6], outC[7]);
}

// ---- 2-sample and 1-sample 8x8x8 (merge kernel, smem weights) ---------------
__device__ __forceinline__ void contract888_2(const float* aA, const float* bA,
                                              const float* aB, const float* bB,
                                              const float* __restrict__ w,
                                              float* outA, float* outB) {
    const ulonglong2* wp = reinterpret_cast<const ulonglong2*>(w);
    ull cA[4] = {0,0,0,0}, cB[4] = {0,0,0,0};
    ulonglong2 W0a = wp[0], W0b = wp[1];
    ulonglong2 W1a = wp[2], W1b = wp[3];
#pragma unroll
    for (int i = 0; i < 8; ++i) {
        ull tA[4] = {0,0,0,0}, tB[4] = {0,0,0,0};
#pragma unroll
        for (int j = 0; j < 8; ++j) {
            const int nidx = i * 8 + j + 2;
            ulonglong2 nWa, nWb;
            if (nidx < 64) {
                nWa = wp[2 * nidx];
                nWb = wp[2 * nidx + 1];
            }
            ull bb = bcast2(bA[j]);
            tA[0] = ffma2(bb, W0a.x, tA[0]);  tA[1] = ffma2(bb, W0a.y, tA[1]);
            tA[2] = ffma2(bb, W0b.x, tA[2]);  tA[3] = ffma2(bb, W0b.y, tA[3]);
            bb = bcast2(bB[j]);
            tB[0] = ffma2(bb, W0a.x, tB[0]);  tB[1] = ffma2(bb, W0a.y, tB[1]);
            tB[2] = ffma2(bb, W0b.x, tB[2]);  tB[3] = ffma2(bb, W0b.y, tB[3]);
            W0a = W1a;  W0b = W1b;
            if (nidx < 64) { W1a = nWa; W1b = nWb; }
        }
        ull ai = bcast2(aA[i]);
        cA[0] = ffma2(ai, tA[0], cA[0]);  cA[1] = ffma2(ai, tA[1], cA[1]);
        cA[2] = ffma2(ai, tA[2], cA[2]);  cA[3] = ffma2(ai, tA[3], cA[3]);
        ai = bcast2(aB[i]);
        cB[0] = ffma2(ai, tB[0], cB[0]);  cB[1] = ffma2(ai, tB[1], cB[1]);
        cB[2] = ffma2(ai, tB[2], cB[2]);  cB[3] = ffma2(ai, tB[3], cB[3]);
    }
    unpack2(cA[0], outA[0], outA[1]);  unpack2(cA[1], outA[2], outA[3]);
    unpack2(cA[2], outA[4], outA[5]);  unpack2(cA[3], outA[6], outA[7]);
    unpack2(cB[0], outB[0], outB[1]);  unpack2(cB[1], outB[2], outB[3]);
    unpack2(cB[2], outB[4], outB[5]);  unpack2(cB[3], outB[6], outB[7]);
}

__device__ __forceinline__ void contract888_1(const float* a, const float* b,
                                              const float* __restrict__ w, float* out) {
    const ulonglong2* wp = reinterpret_cast<const ulonglong2*>(w);
    ull c[4] = {0,0,0,0};
    ulonglong2 W0a = wp[0], W0b = wp[1];
    ulonglong2 W1a = wp[2], W1b = wp[3];
#pragma unroll
    for (int i = 0; i < 8; ++i) {
        ull t[4] = {0,0,0,0};
#pragma unroll
        for (int j = 0; j < 8; ++j) {
            const int nidx = i * 8 + j + 2;
            ulonglong2 nWa, nWb;
            if (nidx < 64) {
                nWa = wp[2 * nidx];
                nWb = wp[2 * nidx + 1];
            }
            ull bb = bcast2(b[j]);
            t[0] = ffma2(bb, W0a.x, t[0]);  t[1] = ffma2(bb, W0a.y, t[1]);
            t[2] = ffma2(bb, W0b.x, t[2]);  t[3] = ffma2(bb, W0b.y, t[3]);
            W0a = W1a;  W0b = W1b;
            if (nidx < 64) { W1a = nWa; W1b = nWb; }
        }
        ull ai = bcast2(a[i]);
        c[0] = ffma2(ai, t[0], c[0]);  c[1] = ffma2(ai, t[1], c[1]);
        c[2] = ffma2(ai, t[2], c[2]);  c[3] = ffma2(ai, t[3], c[3]);
    }
    unpack2(c[0], out[0], out[1]);  unpack2(c[1], out[2], out[3]);
    unpack2(c[2], out[4], out[5]);  unpack2(c[3], out[6], out[7]);
}

__device__ __forceinline__ void scopy4(float* dst, const float* __restrict__ src, int n4) {
    const float4* s = reinterpret_cast<const float4*>(src);
    float4* d = reinterpret_cast<float4*>(dst);
    for (int i = threadIdx.x; i < n4; i += blockDim.x) d[i] = s[i];
}

__device__ __forceinline__ void store_pair(float4* buf, int b, const float* v) {
    buf[(size_t)b * 2 + 0] = make_float4(v[0], v[1], v[2], v[3]);
    buf[(size_t)b * 2 + 1] = make_float4(v[4], v[5], v[6], v[7]);
}

// ------------------------------- kernel 1 ----------------------------------
__global__ void __launch_bounds__(T1, 5)
tn_eighth_kernel(const float* __restrict__ x,
                 const float* __restrict__ w7, const float* __restrict__ w6,
                 const float* __restrict__ w5, const float* __restrict__ w4,
                 const float* __restrict__ w3) {
    extern __shared__ float sw[];

    const int e   = blockIdx.x / BLK_E;      // eighth 0..7
    const int blk = blockIdx.x - e * BLK_E;  // 0..341

    scopy4(sw + E7, w7 + e * 256,   256 / 4);
    scopy4(sw + E6, w6 + e * 1024, 1024 / 4);
    scopy4(sw + E5, w5 + e * 2048, 2048 / 4);
    scopy4(sw + E4, w4 + e * 1024, 1024 / 4);
    scopy4(sw + E3, w3 + e * 512,   512 / 4);
    __syncthreads();

    const int b0 = blk * SPB + threadIdx.x;
    int b1 = b0 + T1;
    int b2 = b0 + 2 * T1;
    if (b1 >= NB) b1 = b0;
    if (b2 >= NB) b2 = b0;

    const float4* xA = reinterpret_cast<const float4*>(x) + (size_t)b0 * 128 + e * 16;
    const float4* xB = reinterpret_cast<const float4*>(x) + (size_t)b1 * 128 + e * 16;
    const float4* xC = reinterpret_cast<const float4*>(x) + (size_t)b2 * 128 + e * 16;

    float stkA0[8], stkA1[8], stkA2[8];
    float stkB0[8], stkB1[8], stkB2[8];
    float stkC0[8], stkC1[8], stkC2[8];

#pragma unroll 1
    for (int m = 0; m < 8; ++m) {
        float4 qA0 = __ldcs(xA + 2 * m);
        float4 qA1 = __ldcs(xA + 2 * m + 1);
        float4 qB0 = __ldcs(xB + 2 * m);
        float4 qB1 = __ldcs(xB + 2 * m + 1);
        float4 qC0 = __ldcs(xC + 2 * m);
        float4 qC1 = __ldcs(xC + 2 * m + 1);

        float laA[4], lbA[4], laB[4], lbB[4], laC[4], lbC[4];
        leaf3(qA0, qB0, qC0, sw + E7 + (2 * m) * 16, laA, laB, laC);
        leaf3(qA1, qB1, qC1, sw + E7 + (2 * m + 1) * 16, lbA, lbB, lbC);

        float curA[8], curB[8], curC[8];
        contract448_3(laA, lbA, laB, lbB, laC, lbC, sw + E6 + m * 128,
                      curA, curB, curC);

        if (!(m & 1)) {
            cp8(stkA0, curA);  cp8(stkB0, curB);  cp8(stkC0, curC);
        } else {
            contract888_3(stkA0, curA, stkB0, curB, stkC0, curC,
                          sw + E5 + (m >> 1) * 512, curA, curB, curC);
            if (!((m >> 1) & 1)) {
                cp8(stkA1, curA);  cp8(stkB1, curB);  cp8(stkC1, curC);
            } else {
                contract888_3(stkA1, curA, stkB1, curB, stkC1, curC,
                              sw + E4 + (m >> 2) * 512, curA, curB, curC);
                if (!((m >> 2) & 1)) {
                    cp8(stkA2, curA);  cp8(stkB2, curB);  cp8(stkC2, curC);
                } else {
                    // m == 7: top of this eighth (w3 node)
                    contract888_3(stkA2, curA, stkB2, curB, stkC2, curC,
                                  sw + E3, curA, curB, curC);
                    float4* eb = g_ebuf + ((size_t)e * NB) * 2;
                    store_pair(eb, b0, curA);
                    store_pair(eb, b1, curB);
                    store_pair(eb, b2, curC);
                }
            }
        }
    }
}

// ------------------------------- kernel 2 ----------------------------------
// 8 warps per CTA, 64 sample-pairs per CTA (2 groups of 32), grid 512.
// Weight staging amortized over 2x pairs vs R14. g_ebuf loads hoisted.
// Stage1: warp -> (group g = warp>>2, w2 node = warp&3).
// Stage2: warp -> (group g = warp>>2, side = (warp>>1)&1, class = warp&1).
// Stage3: warps 0..3 -> (group g = warp>>1, class = warp&1).
__global__ void __launch_bounds__(T2)
tn_merge_kernel(const float* __restrict__ w2, const float* __restrict__ w1,
                const float* __restrict__ w0, float* __restrict__ out) {
    __shared__ float w2s[2048];
    __shared__ float w1s[1024];
    __shared__ float w0s[128];
    __shared__ float x1[4][2][2][32 * 9];  // [w2 node][group][class][lane]
    __shared__ float x2[2][2][2][32 * 9];  // [side][group][class][lane]

    const int warp = threadIdx.x >> 5;
    const int lane = threadIdx.x & 31;

    // stage-1 identity
    const int g1   = warp >> 2;          // group 0/1
    const int node = warp & 3;           // w2 node 0..3
    const int bA1  = blockIdx.x * 64 + g1 * 32 + lane;
    const int bB1  = bA1 + HALF;

    // hoisted g_ebuf loads (before staging, overlap latency)
    float4 pA0 = __ldg(g_ebuf + ((size_t)(2 * node + 0) * NB + bA1) * 2 + 0);
    float4 pA1 = __ldg(g_ebuf + ((size_t)(2 * node + 0) * NB + bA1) * 2 + 1);
    float4 pA2 = __ldg(g_ebuf + ((size_t)(2 * node + 1) * NB + bA1) * 2 + 0);
    float4 pA3 = __ldg(g_ebuf + ((size_t)(2 * node + 1) * NB + bA1) * 2 + 1);
    float4 pB0 = __ldg(g_ebuf + ((size_t)(2 * node + 0) * NB + bB1) * 2 + 0);
    float4 pB1 = __ldg(g_ebuf + ((size_t)(2 * node + 0) * NB + bB1) * 2 + 1);
    float4 pB2 = __ldg(g_ebuf + ((size_t)(2 * node + 1) * NB + bB1) * 2 + 0);
    float4 pB3 = __ldg(g_ebuf + ((size_t)(2 * node + 1) * NB + bB1) * 2 + 1);

    scopy4(w2s, w2, 2048 / 4);
    scopy4(w1s, w1, 1024 / 4);
    scopy4(w0s, w0, 128 / 4);
    __syncthreads();

    // ---- stage 1 ----
    {
        float vA0[8] = {pA0.x, pA0.y, pA0.z, pA0.w, pA1.x, pA1.y, pA1.z, pA1.w};
        float vA1[8] = {pA2.x, pA2.y, pA2.z, pA2.w, pA3.x, pA3.y, pA3.z, pA3.w};
        float vB0[8] = {pB0.x, pB0.y, pB0.z, pB0.w, pB1.x, pB1.y, pB1.z, pB1.w};
        float vB1[8] = {pB2.x, pB2.y, pB2.z, pB2.w, pB3.x, pB3.y, pB3.z, pB3.w};
        float qA[8], qB[8];
        contract888_2(vA0, vA1, vB0, vB1, w2s + node * 512, qA, qB);
#pragma unroll
        for (int k = 0; k < 8; ++k) {
            x1[node][g1][0][lane * 9 + k] = qA[k];
            x1[node][g1][1][lane * 9 + k] = qB[k];
        }
    }
    __syncthreads();

    // ---- stage 2 ----
    {
        const int g    = warp >> 2;
        const int side = (warp >> 1) & 1;
        const int cls  = warp & 1;
        float a[8], b[8], h[8];
#pragma unroll
        for (int k = 0; k < 8; ++k) {
            a[k] = x1[2 * side + 0][g][cls][lane * 9 + k];
            b[k] = x1[2 * side + 1][g][cls][lane * 9 + k];
        }
        contract888_1(a, b, w1s + side * 512, h);
#pragma unroll
        for (int k = 0; k < 8; ++k) x2[side][g][cls][lane * 9 + k] = h[k];
    }
    __syncthreads();

    // ---- stage 3: roots on warps 0..3 ----
    if (warp < 4) {
        const int g   = warp >> 1;
        const int cls = warp & 1;
        const int bo  = blockIdx.x * 64 + g * 32 + lane + (cls ? HALF : 0);
        float hL[8], hR[8];
#pragma unroll
        for (int k = 0; k < 8; ++k) {
            hL[k] = x2[0][g][cls][lane * 9 + k];
            hR[k] = x2[1][g][cls][lane * 9 + k];
        }
        ull acc = 0ull;
#pragma unroll
        for (int i = 0; i < 8; ++i) {
            ull ai = bcast2(hL[i]);
#pragma unroll
            for (int j = 0; j < 8; ++j) {
                ull W = *reinterpret_cast<const ull*>(w0s + (i * 8 + j) * 2);
                acc = ffma2(ffma2(ai, bcast2(hR[j]), 0ull), W, acc);
            }
        }
        float r0, r1;
        unpack2(acc, r0, r1);
        reinterpret_cast<float2*>(out)[bo] = make_float2(r0, r1);
    }
}

extern "C" void kernel_launch(void* const* d_in, const int* in_sizes, int n_in,
                              void* d_out, int out_size) {
    const float* x  = (const float*)d_in[0];
    const float* w7 = (const float*)d_in[1];
    const float* w6 = (const float*)d_in[2];
    const float* w5 = (const float*)d_in[3];
    const float* w4 = (const float*)d_in[4];
    const float* w3 = (const float*)d_in[5];
    const float* w2 = (const float*)d_in[6];
    const float* w1 = (const float*)d_in[7];
    const float* w0 = (const float*)d_in[8];
    float* out = (float*)d_out;

    const size_t smem = SMEM1_FLOATS * sizeof(float);
    cudaFuncSetAttribute(tn_eighth_kernel, cudaFuncAttributeMaxDynamicSharedMemorySize, (int)smem);
    tn_eighth_kernel<<<NBLOCKS1, T1, smem>>>(x, w7, w6, w5, w4, w3);
    tn_merge_kernel<<<NBLOCKS2, T2>>>(w2, w1, w0, out);
}